// round 14
// baseline (speedup 1.0000x reference)
#include <cuda_runtime.h>
#include <cuda_fp16.h>
#include <cstdint>

// Conv2d 3x3 s2 p1 as implicit GEMM with mma.sync, fp16 x fp16, fp32 accum.
// R13: B fragments (fragment-ordered in gmem, no smem) are register
// double-buffered: while kb's MMAs run on q[4], the 4 LDG.128 for the next
// (kb,chunk) are in flight into qn[4] -- prefetch crosses chunk/group
// boundaries since B addresses don't depend on any barrier.
// A path unchanged from R12 (tap-major gather -> smem -> ldmatrix).
// x[16,256,64,64] fp32, w[256,256,3,3] fp32, bias[256] -> out fp32, permuted.
// M = 16384, N = 256, K = 2304 = 12 groups x 3 chunks x 64.
// k' = ((kh*4+cb)*3+kw)*64 + ci,  cin = cb*64 + ci,  c = (kh*4+cb)*3 + kw.

#define CIN    256
#define COUT   256
#define HW     64
#define PP     1024
#define KTOT   2304
#define NCHUNK 36
#define NGROUP 12

#define SWZ(o)  ((o) ^ (((o) >> 3) & 0x70))   // 128B-row swizzle (A)

// fragment-ordered weights: index = (((c*4+wn)*4+kb)*4+ntile)*32 + lane
__device__ __align__(16) uint4 g_wq[NCHUNK * 4 * 4 * 4 * 32];   // 1.18 MB

__global__ void wprep_kernel(const float* __restrict__ w) {
    const int i = blockIdx.x * blockDim.x + threadIdx.x;
    if (i >= NCHUNK * 4 * 4 * 4 * 32) return;
    const int lane  = i & 31;
    int t = i >> 5;
    const int ntile = t & 3; t >>= 2;
    const int kb    = t & 3; t >>= 2;
    const int wn    = t & 3; t >>= 2;
    const int c     = t;                      // 0..35
    uint32_t o[4];
#pragma unroll
    for (int nh = 0; nh < 2; nh++) {
        const int n = wn * 64 + ntile * 16 + nh * 8 + (lane >> 2);
#pragma unroll
        for (int half = 0; half < 2; half++) {
            uint32_t lo[2];
#pragma unroll
            for (int e = 0; e < 2; e++) {
                const int kp = c * 64 + kb * 16 + 2 * (lane & 3) + half * 8 + e;
                const int ci = kp & 63;
                const int tt = kp >> 6;       // == c
                const int kw = tt % 3;
                const int u  = tt / 3;
                const int cb = u & 3;
                const int kh = u >> 2;
                const int cin = cb * 64 + ci;
                const float v = w[(size_t)n * KTOT + cin * 9 + kh * 3 + kw];
                lo[e] = (uint32_t)__half_as_ushort(__float2half_rn(v));
            }
            o[nh * 2 + half] = lo[0] | (lo[1] << 16);
        }
    }
    g_wq[i] = make_uint4(o[0], o[1], o[2], o[3]);
}

__device__ __forceinline__ uint32_t smem_u32_of(const void* p) {
    uint32_t a;
    asm("{ .reg .u64 t; cvta.to.shared.u64 t, %1; cvt.u32.u64 %0, t; }" : "=r"(a) : "l"(p));
    return a;
}

#define LDMATRIX_X4(r0, r1, r2, r3, addr)                                    \
    asm volatile("ldmatrix.sync.aligned.m8n8.x4.shared.b16 {%0,%1,%2,%3}, [%4];" \
                 : "=r"(r0), "=r"(r1), "=r"(r2), "=r"(r3) : "r"(addr))

#define MMA16816F16(d, a, b0, b1)                                            \
    asm volatile("mma.sync.aligned.m16n8k16.row.col.f32.f16.f16.f32 "        \
                 "{%0,%1,%2,%3},{%4,%5,%6,%7},{%8,%9},{%0,%1,%2,%3};"        \
                 : "+f"((d)[0]), "+f"((d)[1]), "+f"((d)[2]), "+f"((d)[3])    \
                 : "r"((a)[0]), "r"((a)[1]), "r"((a)[2]), "r"((a)[3]),       \
                   "r"(b0), "r"(b1))

// smem: A only. 2 group-stages x 3 chunks x 8KB = 48KB.
// Row = 128B = 64 fp16 k'. 64 rows/chunk. SWZ-swizzled.
#define A_CHUNK  8192
#define A_GROUP  24576
#define SMEM_TOTAL 49152

__global__ __launch_bounds__(256, 2)
void conv_mma_kernel(const float* __restrict__ x,
                     const float* __restrict__ bias,
                     float* __restrict__ out)
{
    extern __shared__ char smem[];
    const uint32_t smem_u = smem_u32_of(smem);

    const int tid = threadIdx.x;
    const int lid = tid & 31;
    const int wid = tid >> 5;
    const int mb  = blockIdx.x;          // 0..255
    const int n   = mb >> 4;             // image
    const int oip = mb & 15;             // output-row pair: oi_g in {2*oip, 2*oip+1}

    // ---- A gather geometry: warp = 32 consecutive oj lanes ----
    const int oj_g   = tid & 31;
    const int g      = tid >> 5;          // 8 warps
    const int oi_loc = g & 1;
    const int cs     = (g >> 1) * 16;     // ci subrange [cs, cs+16)
    const int arow   = oi_loc * 32 + oj_g;
    const int yb     = 2 * (2 * oip + oi_loc) - 1;
    const int xm1    = 2 * oj_g - 1;      // x for kw=0 (kw1 = xm1+1, kw2 = xm1+2)
    const float* xbp = x + (size_t)n * CIN * HW * HW;

    const int wm = wid >> 2;   // 0..1  (oi_loc of consumer tile)
    const int wn = wid & 3;    // 0..3  (64-cout slice)

    float acc[2][8][4];
#pragma unroll
    for (int a = 0; a < 2; a++)
#pragma unroll
        for (int b = 0; b < 8; b++)
#pragma unroll
            for (int c = 0; c < 4; c++) acc[a][b][c] = 0.0f;

    // gather + convert + STS for group g3 (regs live only inside this call)
    auto produceA = [&](int g3) {        // g3 = kh*4 + cb
        const int kh = g3 >> 2;
        const int cb = g3 & 3;
        const int y  = yb + kh;
        const bool okY = (y >= 0);
        const bool ok0 = okY & (xm1 >= 0);
        const float* base = xbp + ((size_t)(cb * 64 + cs) << 12) + (y << 6) + xm1;
        uint32_t pk0[8], pk1[8], pk2[8];
#pragma unroll
        for (int jj = 0; jj < 8; jj++) {
            const float* p0 = base + (jj * 2) * 4096;
            const float* p1 = p0 + 4096;
            const float  s0 = ok0 ? __ldg(p0) : 0.0f;
            const float  s1 = ok0 ? __ldg(p1) : 0.0f;
            const float2 f0 = okY ? *(const float2*)(p0 + 1) : make_float2(0.f, 0.f);
            const float2 f1 = okY ? *(const float2*)(p1 + 1) : make_float2(0.f, 0.f);
            pk0[jj] = (uint32_t)__half_as_ushort(__float2half_rn(s0)) |
                      ((uint32_t)__half_as_ushort(__float2half_rn(s1)) << 16);
            pk1[jj] = (uint32_t)__half_as_ushort(__float2half_rn(f0.x)) |
                      ((uint32_t)__half_as_ushort(__float2half_rn(f1.x)) << 16);
            pk2[jj] = (uint32_t)__half_as_ushort(__float2half_rn(f0.y)) |
                      ((uint32_t)__half_as_ushort(__float2half_rn(f1.y)) << 16);
        }
        char* sb = smem + (g3 & 1) * A_GROUP;
        const uint32_t base_b = (uint32_t)(arow * 128 + cs * 2);
        *(uint4*)(sb + 0 * A_CHUNK + SWZ(base_b))      = make_uint4(pk0[0], pk0[1], pk0[2], pk0[3]);
        *(uint4*)(sb + 0 * A_CHUNK + SWZ(base_b + 16)) = make_uint4(pk0[4], pk0[5], pk0[6], pk0[7]);
        *(uint4*)(sb + 1 * A_CHUNK + SWZ(base_b))      = make_uint4(pk1[0], pk1[1], pk1[2], pk1[3]);
        *(uint4*)(sb + 1 * A_CHUNK + SWZ(base_b + 16)) = make_uint4(pk1[4], pk1[5], pk1[6], pk1[7]);
        *(uint4*)(sb + 2 * A_CHUNK + SWZ(base_b))      = make_uint4(pk2[0], pk2[1], pk2[2], pk2[3]);
        *(uint4*)(sb + 2 * A_CHUNK + SWZ(base_b + 16)) = make_uint4(pk2[4], pk2[5], pk2[6], pk2[7]);
    };

    // B fragment pointers: chunk c base = g_wq + c*2048 + wn*512 + lid
    const uint4* bq0 = g_wq + wn * 512 + lid;

    // ---- prologue: A group 0 staged; B (c=0, kb=0) in regs ----
    produceA(0);
    uint4 q[4];
#pragma unroll
    for (int nt = 0; nt < 4; nt++) q[nt] = __ldg(bq0 + nt * 32);
    __syncthreads();

    for (int g3 = 0; g3 < NGROUP; ++g3) {
#pragma unroll
        for (int w = 0; w < 3; ++w) {
            const int c = g3 * 3 + w;

            // Stage (g3+1)&1 writable: its readers (group g3-1) finished
            // before the barrier at the end of the previous group.
            if (w == 0 && g3 + 1 < NGROUP) produceA(g3 + 1);

            const uint32_t ab = smem_u + (g3 & 1) * A_GROUP + w * A_CHUNK;

#pragma unroll
            for (int kb = 0; kb < 4; kb++) {          // 4 x 16 k per chunk
                uint32_t A0[2][4];
#pragma unroll
                for (int mt = 0; mt < 2; mt++) {
                    const int mrow = wm * 32 + mt * 16 + ((lid >> 3) & 1) * 8 + (lid & 7);
                    const int kby  = kb * 32 + (lid >> 4) * 16;
                    LDMATRIX_X4(A0[mt][0], A0[mt][1], A0[mt][2], A0[mt][3],
                                ab + SWZ((uint32_t)(mrow * 128 + kby)));
                }
                // prefetch next (kb, chunk) B fragments: 4 LDG.128, MLP=4
                const int  cn   = (kb < 3) ? c : ((c < NCHUNK - 1) ? c + 1 : c);
                const int  kbn  = (kb < 3) ? kb + 1 : 0;
                const uint4* nq = bq0 + (size_t)cn * 2048 + kbn * 128;
                uint4 qn[4];
#pragma unroll
                for (int nt = 0; nt < 4; nt++) qn[nt] = __ldg(nq + nt * 32);

#pragma unroll
                for (int ntile = 0; ntile < 4; ntile++) {
#pragma unroll
                    for (int mt = 0; mt < 2; mt++) {
                        MMA16816F16(acc[mt][ntile * 2 + 0], A0[mt], q[ntile].x, q[ntile].y);
                        MMA16816F16(acc[mt][ntile * 2 + 1], A0[mt], q[ntile].z, q[ntile].w);
                    }
                }
#pragma unroll
                for (int nt = 0; nt < 4; nt++) q[nt] = qn[nt];
            }
        }
        __syncthreads();   // group boundary: A stage reuse hazard
    }

    // ---- epilogue: bias + permuted store ----
    // m-row r = wm*32 + mt*16 + (lid>>2) (+8): oi_g = 2*oip + wm, oj = r & 31.
    // p = (si*2 + sj)*256 + i*16 + j with si = wm, i = oip, sj = oj&1, j = oj>>1.
#pragma unroll
    for (int mt = 0; mt < 2; mt++) {
#pragma unroll
        for (int nt = 0; nt < 8; nt++) {
            const int oj = mt * 16 + (lid >> 2);
            const int sj = oj & 1;
            const int p0 = ((wm * 2 + sj) << 8) + (oip << 4) + (oj >> 1);
            const int p1 = p0 + 4;                      // oj+8 -> j+4, same sj
            const int c0 = wn * 64 + nt * 8 + (lid & 3) * 2;
            const float2 bv = *(const float2*)&bias[c0];
            float* o0 = out + ((size_t)(n * COUT + c0)) * PP;
            float* o1 = o0 + PP;
            o0[p0] = acc[mt][nt][0] + bv.x;
            o1[p0] = acc[mt][nt][1] + bv.y;
            o0[p1] = acc[mt][nt][2] + bv.x;
            o1[p1] = acc[mt][nt][3] + bv.y;
        }
    }
}

extern "C" void kernel_launch(void* const* d_in, const int* in_sizes, int n_in,
                              void* d_out, int out_size)
{
    (void)in_sizes; (void)n_in; (void)out_size;
    const float* x    = (const float*)d_in[0];
    const float* wgt  = (const float*)d_in[1];
    const float* bias = (const float*)d_in[2];
    float* out        = (float*)d_out;

    wprep_kernel<<<(NCHUNK * 4 * 4 * 4 * 32 + 255) / 256, 256>>>(wgt);

    cudaFuncSetAttribute(conv_mma_kernel,
                         cudaFuncAttributeMaxDynamicSharedMemorySize, SMEM_TOTAL);
    conv_mma_kernel<<<256, 256, SMEM_TOTAL>>>(x, bias, out);
}

// round 15
// speedup vs baseline: 1.3846x; 1.3846x over previous
#include <cuda_runtime.h>
#include <cuda_fp16.h>
#include <cstdint>

// Conv2d 3x3 s2 p1 as implicit GEMM with mma.sync, fp16 x fp16, fp32 accum.
// R14 = R12 structure (B fragment-ordered in gmem, A via smem) plus:
//  (1) prefetch.global.L1 of chunk c+1's B fragments at top of chunk c
//      (zero registers, kills the per-kb B LDG latency exposure);
//  (2) produceA split into two half-bursts (w=0: jj 0-3, w=1: jj 4-7) to
//      smooth producer stalls and halve burst register pressure.
// x[16,256,64,64] fp32, w[256,256,3,3] fp32, bias[256] -> out fp32, permuted.
// M = 16384, N = 256, K = 2304 = 12 groups x 3 chunks x 64.
// k' = ((kh*4+cb)*3+kw)*64 + ci,  cin = cb*64 + ci,  c = (kh*4+cb)*3 + kw.

#define CIN    256
#define COUT   256
#define HW     64
#define PP     1024
#define KTOT   2304
#define NCHUNK 36
#define NGROUP 12

#define SWZ(o)  ((o) ^ (((o) >> 3) & 0x70))   // 128B-row swizzle (A)

// fragment-ordered weights: index = (((c*4+wn)*4+kb)*4+ntile)*32 + lane
__device__ __align__(16) uint4 g_wq[NCHUNK * 4 * 4 * 4 * 32];   // 1.18 MB

__global__ void wprep_kernel(const float* __restrict__ w) {
    const int i = blockIdx.x * blockDim.x + threadIdx.x;
    if (i >= NCHUNK * 4 * 4 * 4 * 32) return;
    const int lane  = i & 31;
    int t = i >> 5;
    const int ntile = t & 3; t >>= 2;
    const int kb    = t & 3; t >>= 2;
    const int wn    = t & 3; t >>= 2;
    const int c     = t;                      // 0..35
    uint32_t o[4];
#pragma unroll
    for (int nh = 0; nh < 2; nh++) {
        const int n = wn * 64 + ntile * 16 + nh * 8 + (lane >> 2);
#pragma unroll
        for (int half = 0; half < 2; half++) {
            uint32_t lo[2];
#pragma unroll
            for (int e = 0; e < 2; e++) {
                const int kp = c * 64 + kb * 16 + 2 * (lane & 3) + half * 8 + e;
                const int ci = kp & 63;
                const int tt = kp >> 6;       // == c
                const int kw = tt % 3;
                const int u  = tt / 3;
                const int cb = u & 3;
                const int kh = u >> 2;
                const int cin = cb * 64 + ci;
                const float v = w[(size_t)n * KTOT + cin * 9 + kh * 3 + kw];
                lo[e] = (uint32_t)__half_as_ushort(__float2half_rn(v));
            }
            o[nh * 2 + half] = lo[0] | (lo[1] << 16);
        }
    }
    g_wq[i] = make_uint4(o[0], o[1], o[2], o[3]);
}

__device__ __forceinline__ uint32_t smem_u32_of(const void* p) {
    uint32_t a;
    asm("{ .reg .u64 t; cvta.to.shared.u64 t, %1; cvt.u32.u64 %0, t; }" : "=r"(a) : "l"(p));
    return a;
}

#define LDMATRIX_X4(r0, r1, r2, r3, addr)                                    \
    asm volatile("ldmatrix.sync.aligned.m8n8.x4.shared.b16 {%0,%1,%2,%3}, [%4];" \
                 : "=r"(r0), "=r"(r1), "=r"(r2), "=r"(r3) : "r"(addr))

#define MMA16816F16(d, a, b0, b1)                                            \
    asm volatile("mma.sync.aligned.m16n8k16.row.col.f32.f16.f16.f32 "        \
                 "{%0,%1,%2,%3},{%4,%5,%6,%7},{%8,%9},{%0,%1,%2,%3};"        \
                 : "+f"((d)[0]), "+f"((d)[1]), "+f"((d)[2]), "+f"((d)[3])    \
                 : "r"((a)[0]), "r"((a)[1]), "r"((a)[2]), "r"((a)[3]),       \
                   "r"(b0), "r"(b1))

// smem: A only. 2 group-stages x 3 chunks x 8KB = 48KB.
// Row = 128B = 64 fp16 k'. 64 rows/chunk. SWZ-swizzled.
#define A_CHUNK  8192
#define A_GROUP  24576
#define SMEM_TOTAL 49152

__global__ __launch_bounds__(256, 2)
void conv_mma_kernel(const float* __restrict__ x,
                     const float* __restrict__ bias,
                     float* __restrict__ out)
{
    extern __shared__ char smem[];
    const uint32_t smem_u = smem_u32_of(smem);

    const int tid = threadIdx.x;
    const int lid = tid & 31;
    const int wid = tid >> 5;
    const int mb  = blockIdx.x;          // 0..255
    const int n   = mb >> 4;             // image
    const int oip = mb & 15;             // output-row pair: oi_g in {2*oip, 2*oip+1}

    // ---- A gather geometry: warp = 32 consecutive oj lanes ----
    const int oj_g   = tid & 31;
    const int g      = tid >> 5;          // 8 warps
    const int oi_loc = g & 1;
    const int cs     = (g >> 1) * 16;     // ci subrange [cs, cs+16)
    const int arow   = oi_loc * 32 + oj_g;
    const int yb     = 2 * (2 * oip + oi_loc) - 1;
    const int xm1    = 2 * oj_g - 1;      // x for kw=0 (kw1 = xm1+1, kw2 = xm1+2)
    const float* xbp = x + (size_t)n * CIN * HW * HW;

    const int wm = wid >> 2;   // 0..1  (oi_loc of consumer tile)
    const int wn = wid & 3;    // 0..3  (64-cout slice)

    float acc[2][8][4];
#pragma unroll
    for (int a = 0; a < 2; a++)
#pragma unroll
        for (int b = 0; b < 8; b++)
#pragma unroll
            for (int c = 0; c < 4; c++) acc[a][b][c] = 0.0f;

    // half-burst A producer: h=0 -> jj 0..3, h=1 -> jj 4..7
    auto produceA = [&](int g3, int h) {        // g3 = kh*4 + cb
        const int kh = g3 >> 2;
        const int cb = g3 & 3;
        const int y  = yb + kh;
        const bool okY = (y >= 0);
        const bool ok0 = okY & (xm1 >= 0);
        const float* base = xbp + ((size_t)(cb * 64 + cs) << 12) + (y << 6) + xm1
                          + (size_t)(h * 8) * 4096;
        uint32_t pk0[4], pk1[4], pk2[4];
#pragma unroll
        for (int jj = 0; jj < 4; jj++) {
            const float* p0 = base + (jj * 2) * 4096;
            const float* p1 = p0 + 4096;
            const float  s0 = ok0 ? __ldg(p0) : 0.0f;
            const float  s1 = ok0 ? __ldg(p1) : 0.0f;
            const float2 f0 = okY ? *(const float2*)(p0 + 1) : make_float2(0.f, 0.f);
            const float2 f1 = okY ? *(const float2*)(p1 + 1) : make_float2(0.f, 0.f);
            pk0[jj] = (uint32_t)__half_as_ushort(__float2half_rn(s0)) |
                      ((uint32_t)__half_as_ushort(__float2half_rn(s1)) << 16);
            pk1[jj] = (uint32_t)__half_as_ushort(__float2half_rn(f0.x)) |
                      ((uint32_t)__half_as_ushort(__float2half_rn(f1.x)) << 16);
            pk2[jj] = (uint32_t)__half_as_ushort(__float2half_rn(f0.y)) |
                      ((uint32_t)__half_as_ushort(__float2half_rn(f1.y)) << 16);
        }
        char* sb = smem + (g3 & 1) * A_GROUP;
        const uint32_t base_b = (uint32_t)(arow * 128 + cs * 2 + h * 16);
        *(uint4*)(sb + 0 * A_CHUNK + SWZ(base_b)) = make_uint4(pk0[0], pk0[1], pk0[2], pk0[3]);
        *(uint4*)(sb + 1 * A_CHUNK + SWZ(base_b)) = make_uint4(pk1[0], pk1[1], pk1[2], pk1[3]);
        *(uint4*)(sb + 2 * A_CHUNK + SWZ(base_b)) = make_uint4(pk2[0], pk2[1], pk2[2], pk2[3]);
    };

    // B fragment pointer: chunk c base = g_wq + c*2048 + wn*512 (+ lid for LDG)
    const uint4* bqw = g_wq + wn * 512;

    // ---- prologue ----
    produceA(0, 0);
    produceA(0, 1);
    __syncthreads();

    for (int g3 = 0; g3 < NGROUP; ++g3) {
#pragma unroll
        for (int w = 0; w < 3; ++w) {
            const int c = g3 * 3 + w;

            // L1-prefetch next chunk's B fragments for this warp (8KB, 2 instr)
            if (c + 1 < NCHUNK) {
                const char* pf = (const char*)(bqw + (size_t)(c + 1) * 2048) + lid * 128;
                asm volatile("prefetch.global.L1 [%0];" :: "l"(pf));
                asm volatile("prefetch.global.L1 [%0];" :: "l"(pf + 4096));
            }

            // Stage (g3+1)&1 writable: its readers (group g3-1) finished
            // before the barrier at the end of the previous group.
            if (w < 2 && g3 + 1 < NGROUP) produceA(g3 + 1, w);

            const uint32_t ab = smem_u + (g3 & 1) * A_GROUP + w * A_CHUNK;
            const uint4* bq = bqw + (size_t)c * 2048 + lid;

#pragma unroll
            for (int kb = 0; kb < 4; kb++) {          // 4 x 16 k per chunk
                uint32_t A0[2][4];
#pragma unroll
                for (int mt = 0; mt < 2; mt++) {
                    const int mrow = wm * 32 + mt * 16 + ((lid >> 3) & 1) * 8 + (lid & 7);
                    const int kby  = kb * 32 + (lid >> 4) * 16;
                    LDMATRIX_X4(A0[mt][0], A0[mt][1], A0[mt][2], A0[mt][3],
                                ab + SWZ((uint32_t)(mrow * 128 + kby)));
                }
#pragma unroll
                for (int ntile = 0; ntile < 4; ntile++) {
                    const uint4 q = __ldg(bq + kb * 128 + ntile * 32);
#pragma unroll
                    for (int mt = 0; mt < 2; mt++) {
                        MMA16816F16(acc[mt][ntile * 2 + 0], A0[mt], q.x, q.y);
                        MMA16816F16(acc[mt][ntile * 2 + 1], A0[mt], q.z, q.w);
                    }
                }
            }
        }
        __syncthreads();   // group boundary: A stage reuse hazard
    }

    // ---- epilogue: bias + permuted store ----
    // m-row r = wm*32 + mt*16 + (lid>>2) (+8): oi_g = 2*oip + wm, oj = r & 31.
    // p = (si*2 + sj)*256 + i*16 + j with si = wm, i = oip, sj = oj&1, j = oj>>1.
#pragma unroll
    for (int mt = 0; mt < 2; mt++) {
#pragma unroll
        for (int nt = 0; nt < 8; nt++) {
            const int oj = mt * 16 + (lid >> 2);
            const int sj = oj & 1;
            const int p0 = ((wm * 2 + sj) << 8) + (oip << 4) + (oj >> 1);
            const int p1 = p0 + 4;                      // oj+8 -> j+4, same sj
            const int c0 = wn * 64 + nt * 8 + (lid & 3) * 2;
            const float2 bv = *(const float2*)&bias[c0];
            float* o0 = out + ((size_t)(n * COUT + c0)) * PP;
            float* o1 = o0 + PP;
            o0[p0] = acc[mt][nt][0] + bv.x;
            o1[p0] = acc[mt][nt][1] + bv.y;
            o0[p1] = acc[mt][nt][2] + bv.x;
            o1[p1] = acc[mt][nt][3] + bv.y;
        }
    }
}

extern "C" void kernel_launch(void* const* d_in, const int* in_sizes, int n_in,
                              void* d_out, int out_size)
{
    (void)in_sizes; (void)n_in; (void)out_size;
    const float* x    = (const float*)d_in[0];
    const float* wgt  = (const float*)d_in[1];
    const float* bias = (const float*)d_in[2];
    float* out        = (float*)d_out;

    wprep_kernel<<<(NCHUNK * 4 * 4 * 4 * 32 + 255) / 256, 256>>>(wgt);

    cudaFuncSetAttribute(conv_mma_kernel,
                         cudaFuncAttributeMaxDynamicSharedMemorySize, SMEM_TOTAL);
    conv_mma_kernel<<<256, 256, SMEM_TOTAL>>>(x, bias, out);
}

// round 17
// speedup vs baseline: 1.4686x; 1.0607x over previous
#include <cuda_runtime.h>
#include <cuda_fp16.h>
#include <cstdint>

// Conv2d 3x3 s2 p1 as implicit GEMM with mma.sync, fp16 x fp16, fp32 accum.
// R15: B fragments stay fragment-ordered in gmem (g_wq, as R12) but are staged
// through smem via cp.async.cg (double-buffered, issued one chunk ahead) and
// consumed with conflict-free LDS.128 -- no ldmatrix for B, no exposed L2
// latency in the MMA loop. A path identical to R12 (tap-major group gather).
// x[16,256,64,64] fp32, w[256,256,3,3] fp32, bias[256] -> out fp32, permuted.
// M = 16384, N = 256, K = 2304 = 12 groups x 3 chunks x 64.
// k' = ((kh*4+cb)*3+kw)*64 + ci,  cin = cb*64 + ci,  c = (kh*4+cb)*3 + kw.

#define CIN    256
#define COUT   256
#define HW     64
#define PP     1024
#define KTOT   2304
#define NCHUNK 36
#define NGROUP 12

#define SWZ(o)  ((o) ^ (((o) >> 3) & 0x70))   // 128B-row swizzle (A)

// fragment-ordered weights: index = (((c*4+wn)*4+kb)*4+ntile)*32 + lane
__device__ __align__(16) uint4 g_wq[NCHUNK * 4 * 4 * 4 * 32];   // 1.18 MB

__global__ void wprep_kernel(const float* __restrict__ w) {
    const int i = blockIdx.x * blockDim.x + threadIdx.x;
    if (i >= NCHUNK * 4 * 4 * 4 * 32) return;
    const int lane  = i & 31;
    int t = i >> 5;
    const int ntile = t & 3; t >>= 2;
    const int kb    = t & 3; t >>= 2;
    const int wn    = t & 3; t >>= 2;
    const int c     = t;                      // 0..35
    uint32_t o[4];
#pragma unroll
    for (int nh = 0; nh < 2; nh++) {
        const int n = wn * 64 + ntile * 16 + nh * 8 + (lane >> 2);
#pragma unroll
        for (int half = 0; half < 2; half++) {
            uint32_t lo[2];
#pragma unroll
            for (int e = 0; e < 2; e++) {
                const int kp = c * 64 + kb * 16 + 2 * (lane & 3) + half * 8 + e;
                const int ci = kp & 63;
                const int tt = kp >> 6;       // == c
                const int kw = tt % 3;
                const int u  = tt / 3;
                const int cb = u & 3;
                const int kh = u >> 2;
                const int cin = cb * 64 + ci;
                const float v = w[(size_t)n * KTOT + cin * 9 + kh * 3 + kw];
                lo[e] = (uint32_t)__half_as_ushort(__float2half_rn(v));
            }
            o[nh * 2 + half] = lo[0] | (lo[1] << 16);
        }
    }
    g_wq[i] = make_uint4(o[0], o[1], o[2], o[3]);
}

__device__ __forceinline__ uint32_t smem_u32_of(const void* p) {
    uint32_t a;
    asm("{ .reg .u64 t; cvta.to.shared.u64 t, %1; cvt.u32.u64 %0, t; }" : "=r"(a) : "l"(p));
    return a;
}

#define LDMATRIX_X4(r0, r1, r2, r3, addr)                                    \
    asm volatile("ldmatrix.sync.aligned.m8n8.x4.shared.b16 {%0,%1,%2,%3}, [%4];" \
                 : "=r"(r0), "=r"(r1), "=r"(r2), "=r"(r3) : "r"(addr))

#define MMA16816F16(d, a, b0, b1)                                            \
    asm volatile("mma.sync.aligned.m16n8k16.row.col.f32.f16.f16.f32 "        \
                 "{%0,%1,%2,%3},{%4,%5,%6,%7},{%8,%9},{%0,%1,%2,%3};"        \
                 : "+f"((d)[0]), "+f"((d)[1]), "+f"((d)[2]), "+f"((d)[3])    \
                 : "r"((a)[0]), "r"((a)[1]), "r"((a)[2]), "r"((a)[3]),       \
                   "r"(b0), "r"(b1))

#define CP_ASYNC16(dst, src) \
    asm volatile("cp.async.cg.shared.global [%0], [%1], 16;" :: "r"(dst), "l"(src))

// smem: A [0, 48KB): 2 group-stages x 3 chunks x 8KB (SWZ 128B rows).
//       B [48KB, 112KB): 2 chunk-stages x 32KB, LINEAR fragment order.
#define A_CHUNK  8192
#define A_GROUP  24576
#define B_BASE   49152
#define B_STAGE  32768
#define SMEM_TOTAL 114688

__global__ __launch_bounds__(256, 2)
void conv_mma_kernel(const float* __restrict__ x,
                     const float* __restrict__ bias,
                     float* __restrict__ out)
{
    extern __shared__ char smem[];
    const uint32_t smem_u = smem_u32_of(smem);

    const int tid = threadIdx.x;
    const int lid = tid & 31;
    const int wid = tid >> 5;
    const int mb  = blockIdx.x;          // 0..255
    const int n   = mb >> 4;             // image
    const int oip = mb & 15;             // output-row pair: oi_g in {2*oip, 2*oip+1}

    // ---- A gather geometry: warp = 32 consecutive oj lanes ----
    const int oj_g   = tid & 31;
    const int g      = tid >> 5;          // 8 warps
    const int oi_loc = g & 1;
    const int cs     = (g >> 1) * 16;     // ci subrange [cs, cs+16)
    const int arow   = oi_loc * 32 + oj_g;
    const int yb     = 2 * (2 * oip + oi_loc) - 1;
    const int xm1    = 2 * oj_g - 1;      // x for kw=0 (kw1 = xm1+1, kw2 = xm1+2)
    const float* xbp = x + (size_t)n * CIN * HW * HW;

    const int wm = wid >> 2;   // 0..1  (oi_loc of consumer tile)
    const int wn = wid & 3;    // 0..3  (64-cout slice)

    float acc[2][8][4];
#pragma unroll
    for (int a = 0; a < 2; a++)
#pragma unroll
        for (int b = 0; b < 8; b++)
#pragma unroll
            for (int c = 0; c < 4; c++) acc[a][b][c] = 0.0f;

    // gather + convert + STS for group g3 (regs live only inside this call)
    auto produceA = [&](int g3) {        // g3 = kh*4 + cb
        const int kh = g3 >> 2;
        const int cb = g3 & 3;
        const int y  = yb + kh;
        const bool okY = (y >= 0);
        const bool ok0 = okY & (xm1 >= 0);
        const float* base = xbp + ((size_t)(cb * 64 + cs) << 12) + (y << 6) + xm1;
        uint32_t pk0[8], pk1[8], pk2[8];
#pragma unroll
        for (int jj = 0; jj < 8; jj++) {
            const float* p0 = base + (jj * 2) * 4096;
            const float* p1 = p0 + 4096;
            const float  s0 = ok0 ? __ldg(p0) : 0.0f;
            const float  s1 = ok0 ? __ldg(p1) : 0.0f;
            const float2 f0 = okY ? *(const float2*)(p0 + 1) : make_float2(0.f, 0.f);
            const float2 f1 = okY ? *(const float2*)(p1 + 1) : make_float2(0.f, 0.f);
            pk0[jj] = (uint32_t)__half_as_ushort(__float2half_rn(s0)) |
                      ((uint32_t)__half_as_ushort(__float2half_rn(s1)) << 16);
            pk1[jj] = (uint32_t)__half_as_ushort(__float2half_rn(f0.x)) |
                      ((uint32_t)__half_as_ushort(__float2half_rn(f1.x)) << 16);
            pk2[jj] = (uint32_t)__half_as_ushort(__float2half_rn(f0.y)) |
                      ((uint32_t)__half_as_ushort(__float2half_rn(f1.y)) << 16);
        }
        char* sb = smem + (g3 & 1) * A_GROUP;
        const uint32_t base_b = (uint32_t)(arow * 128 + cs * 2);
        *(uint4*)(sb + 0 * A_CHUNK + SWZ(base_b))      = make_uint4(pk0[0], pk0[1], pk0[2], pk0[3]);
        *(uint4*)(sb + 0 * A_CHUNK + SWZ(base_b + 16)) = make_uint4(pk0[4], pk0[5], pk0[6], pk0[7]);
        *(uint4*)(sb + 1 * A_CHUNK + SWZ(base_b))      = make_uint4(pk1[0], pk1[1], pk1[2], pk1[3]);
        *(uint4*)(sb + 1 * A_CHUNK + SWZ(base_b + 16)) = make_uint4(pk1[4], pk1[5], pk1[6], pk1[7]);
        *(uint4*)(sb + 2 * A_CHUNK + SWZ(base_b))      = make_uint4(pk2[0], pk2[1], pk2[2], pk2[3]);
        *(uint4*)(sb + 2 * A_CHUNK + SWZ(base_b + 16)) = make_uint4(pk2[4], pk2[5], pk2[6], pk2[7]);
    };

    // B chunk copy: 32KB linear, 8 x 16B per thread, perfectly coalesced.
    auto issueB = [&](int c) {
        const uint32_t bb = smem_u + B_BASE + (c & 1) * B_STAGE + tid * 16;
        const char* src = (const char*)(g_wq + (size_t)c * 2048) + tid * 16;
#pragma unroll
        for (int i = 0; i < 8; i++)
            CP_ASYNC16(bb + i * 4096, src + i * 4096);
        asm volatile("cp.async.commit_group;");
    };

    // ---- prologue ----
    produceA(0);
    issueB(0);

    for (int g3 = 0; g3 < NGROUP; ++g3) {
#pragma unroll
        for (int w = 0; w < 3; ++w) {
            const int c = g3 * 3 + w;

            asm volatile("cp.async.wait_group 0;");   // B(c) landed
            __syncthreads();                          // stage visibility + reuse
            if (c + 1 < NCHUNK) issueB(c + 1);        // fills stage (c+1)&1

            // A stage (g3+1)&1: last readers were group g3-1 (>=3 barriers ago)
            if (w == 0 && g3 + 1 < NGROUP) produceA(g3 + 1);

            const uint32_t ab = smem_u + (g3 & 1) * A_GROUP + w * A_CHUNK;
            const uint4* bq = (const uint4*)(smem + B_BASE + (c & 1) * B_STAGE)
                              + wn * 512 + lid;

#pragma unroll
            for (int kb = 0; kb < 4; kb++) {          // 4 x 16 k per chunk
                uint32_t A0[2][4];
#pragma unroll
                for (int mt = 0; mt < 2; mt++) {
                    const int mrow = wm * 32 + mt * 16 + ((lid >> 3) & 1) * 8 + (lid & 7);
                    const int kby  = kb * 32 + (lid >> 4) * 16;
                    LDMATRIX_X4(A0[mt][0], A0[mt][1], A0[mt][2], A0[mt][3],
                                ab + SWZ((uint32_t)(mrow * 128 + kby)));
                }
#pragma unroll
                for (int ntile = 0; ntile < 4; ntile++) {
                    const uint4 q = bq[kb * 128 + ntile * 32];   // LDS.128
#pragma unroll
                    for (int mt = 0; mt < 2; mt++) {
                        MMA16816F16(acc[mt][ntile * 2 + 0], A0[mt], q.x, q.y);
                        MMA16816F16(acc[mt][ntile * 2 + 1], A0[mt], q.z, q.w);
                    }
                }
            }
        }
    }

    // ---- epilogue: bias + permuted store ----
    // m-row r = wm*32 + mt*16 + (lid>>2) (+8): oi_g = 2*oip + wm, oj = r & 31.
    // p = (si*2 + sj)*256 + i*16 + j with si = wm, i = oip, sj = oj&1, j = oj>>1.
#pragma unroll
    for (int mt = 0; mt < 2; mt++) {
#pragma unroll
        for (int nt = 0; nt < 8; nt++) {
            const int oj = mt * 16 + (lid >> 2);
            const int sj = oj & 1;
            const int p0 = ((wm * 2 + sj) << 8) + (oip << 4) + (oj >> 1);
            const int p1 = p0 + 4;                      // oj+8 -> j+4, same sj
            const int c0 = wn * 64 + nt * 8 + (lid & 3) * 2;
            const float2 bv = *(const float2*)&bias[c0];
            float* o0 = out + ((size_t)(n * COUT + c0)) * PP;
            float* o1 = o0 + PP;
            o0[p0] = acc[mt][nt][0] + bv.x;
            o1[p0] = acc[mt][nt][1] + bv.y;
            o0[p1] = acc[mt][nt][2] + bv.x;
            o1[p1] = acc[mt][nt][3] + bv.y;
        }
    }
}

extern "C" void kernel_launch(void* const* d_in, const int* in_sizes, int n_in,
                              void* d_out, int out_size)
{
    (void)in_sizes; (void)n_in; (void)out_size;
    const float* x    = (const float*)d_in[0];
    const float* wgt  = (const float*)d_in[1];
    const float* bias = (const float*)d_in[2];
    float* out        = (float*)d_out;

    wprep_kernel<<<(NCHUNK * 4 * 4 * 4 * 32 + 255) / 256, 256>>>(wgt);

    cudaFuncSetAttribute(conv_mma_kernel,
                         cudaFuncAttributeMaxDynamicSharedMemorySize, SMEM_TOTAL);
    conv_mma_kernel<<<256, 256, SMEM_TOTAL>>>(x, bias, out);
}